// round 11
// baseline (speedup 1.0000x reference)
#include <cuda_runtime.h>
#include <cstdint>

// Problem constants
#define SQ 50
#define SP 3
#define SS 64
#define WORDS 256      // words per block
#define THREADS 512    // 16 warps; 2 octets of 8 warps; thread owns 4 words
#define TROW 158       // padded row stride: 30i mod 32, half-warp phases conflict-free

// Packed heads: ha[q][j(32)][4] = {h0s0,h0s1,h1s0,h1s1}
//               hcp[q][jp(16)][4] = {h2(2jp)s0,h2(2jp)s1, h2(2jp+1)s0,h2(2jp+1)s1}
#define HA_TOTAL (SQ * 128)   // 6400
#define HCP_TOTAL (SQ * 64)   // 3200

// smem float offsets
#define OFF_HCP  HA_TOTAL               // 6400
#define OFF_HR   (OFF_HCP + HCP_TOTAL)  // 9600
#define OFF_PART (OFF_HR + SS)          // 9664 (7*256 = 1792)
#define OFF_RED  (OFF_PART + 7*WORDS)   // 11456 (16 floats = 8 doubles)
#define OFF_T    (OFF_RED + 16)         // 11472 (x4B = 45888, 16B aligned)
#define SMEM_FLOATS (OFF_T + WORDS * TROW)   // 51920 floats = 207680 B

__device__ double       g_accum;
__device__ unsigned int g_count;
__device__ float        g_ha[HA_TOTAL];
__device__ float        g_hcp[HCP_TOTAL];
__device__ float        g_hr[SS];

__device__ __forceinline__ float softplus20(float x) {
    float y = x * 20.0f;
    return fmaxf(y, 0.0f) + log1pf(expf(-fabsf(y)));
}

// ---------------------------------------------------------------------------
__global__ void prep_kernel(const float* __restrict__ heads_param,
                            const float* __restrict__ hr_param) {
    const int tid = threadIdx.x;

    if (blockIdx.x == 0 && tid == 0) { g_accum = 0.0; g_count = 0u; }

    __shared__ float s_hr[SS];
    if (tid < SS) s_hr[tid] = softplus20(hr_param[tid]);
    __syncthreads();
    if (blockIdx.x == 0 && tid < SS) {
        float s = 0.0f;
        #pragma unroll
        for (int i = 0; i < SS; i++) s += s_hr[i];
        s = fmaxf(s, 1e-12f);
        g_hr[tid] = (s_hr[tid] / s + 0.001f / (float)SS) / 1.001f;
    }

    const int stride = blockDim.x * gridDim.x;
    for (int i = blockIdx.x * blockDim.x + tid; i < SS * SQ; i += stride) {
        int s = i / SQ;
        int q = i - s * SQ;
        const float* hp = heads_param + (s * SQ + q) * SP;
        float h0 = softplus20(hp[0]);
        float h1 = softplus20(hp[1]);
        float h2 = softplus20(hp[2]);
        float inv = 1.0f / fmaxf(h0 + h1 + h2, 1e-12f);
        h0 *= inv; h1 *= inv; h2 *= inv;
        int j = s >> 1, o = s & 1;
        int jp = j >> 1, jo = j & 1;
        g_ha[q * 128 + j * 4 + 0 + o]       = h0;
        g_ha[q * 128 + j * 4 + 2 + o]       = h1;
        g_hcp[q * 64 + jp * 4 + jo * 2 + o] = h2;
    }
}

// ---------------------------------------------------------------------------
// Apply one q to 4 words x 4 head-pairs.
// ---------------------------------------------------------------------------
__device__ __forceinline__ void proc_q4(
    const ulonglong2* __restrict__ ha,   // + eighth*4, entries j=0..3
    const ulonglong2* __restrict__ hcp,  // + eighth*2, entries jp=0..1
    const uint64_t* __restrict__ R0,     // [4] words
    const uint64_t* __restrict__ R1,
    uint64_t acc[4][4])
{
    #pragma unroll
    for (int jp = 0; jp < 2; jp++) {
        ulonglong2 HcP = hcp[jp];
        ulonglong2 Ha0 = ha[2 * jp];
        ulonglong2 Ha1 = ha[2 * jp + 1];
        #pragma unroll
        for (int k = 0; k < 4; k++) {
            uint64_t d, e;
            asm("fma.rn.f32x2 %0, %1, %2, %3;" : "=l"(d) : "l"(Ha0.x), "l"(R0[k]), "l"(HcP.x));
            asm("fma.rn.f32x2 %0, %1, %2, %3;" : "=l"(d) : "l"(Ha0.y), "l"(R1[k]), "l"(d));
            asm("mul.rn.f32x2 %0, %1, %2;" : "=l"(acc[k][2*jp]) : "l"(acc[k][2*jp]), "l"(d));
            asm("fma.rn.f32x2 %0, %1, %2, %3;" : "=l"(e) : "l"(Ha1.x), "l"(R0[k]), "l"(HcP.y));
            asm("fma.rn.f32x2 %0, %1, %2, %3;" : "=l"(e) : "l"(Ha1.y), "l"(R1[k]), "l"(e));
            asm("mul.rn.f32x2 %0, %1, %2;" : "=l"(acc[k][2*jp+1]) : "l"(acc[k][2*jp+1]), "l"(e));
        }
    }
}

// ---------------------------------------------------------------------------
// Main: octet g = wid>>3 covers words [g*128,(g+1)*128); eighth = wid&7 handles
// head pairs eighth*4..+3 (heads 8e..8e+7). Thread words: lane + 32k, k<4.
// ---------------------------------------------------------------------------
__global__ void __launch_bounds__(THREADS, 1)
main_kernel(const float* __restrict__ pauli,
            const float* __restrict__ coeff,
            float* __restrict__ out,
            int N, int nblocks) {
    extern __shared__ float smem[];
    float*  sh_ha   = smem;
    float*  sh_hcp  = smem + OFF_HCP;
    float*  sh_hr   = smem + OFF_HR;
    float*  sh_part = smem + OFF_PART;
    double* sh_red  = (double*)(smem + OFF_RED);
    float*  sh_t    = smem + OFF_T;

    const int tid  = threadIdx.x;
    const int wid  = tid >> 5;
    const int lane = tid & 31;

    // Stage heads tables
    {
        const float4* src = (const float4*)g_ha;
        float4*       dst = (float4*)sh_ha;
        #pragma unroll
        for (int i = tid; i < HA_TOTAL / 4; i += THREADS) dst[i] = src[i];
        const float4* src2 = (const float4*)g_hcp;
        float4*       dst2 = (float4*)sh_hcp;
        #pragma unroll
        for (int i = tid; i < HCP_TOTAL / 4; i += THREADS) dst2[i] = src2[i];
    }
    if (tid < SS) sh_hr[tid] = g_hr[tid];

    // Stage pauli tile: float2 coalesced reads, padded-row scatter
    const int base  = blockIdx.x * WORDS;
    const int valid = min(WORDS, N - base);
    const float2* gsrc2 = (const float2*)(pauli + (size_t)base * (SQ * SP));
    for (int i = tid; i < valid * 75; i += THREADS) {
        int w = i / 75;
        int k = i - w * 75;
        *(float2*)(sh_t + w * TROW + 2 * k) = gsrc2[i];
    }
    __syncthreads();

    const int eighth = wid & 7;
    const int group  = wid >> 3;
    int w4[4];
    const float* trow[4];
    #pragma unroll
    for (int k = 0; k < 4; k++) {
        w4[k] = group * 128 + lane + 32 * k;
        trow[k] = sh_t + w4[k] * TROW;
    }

    uint64_t acc[4][4];
    #pragma unroll
    for (int k = 0; k < 4; k++)
        #pragma unroll
        for (int j = 0; j < 4; j++) acc[k][j] = 0x3F8000003F800000ull;
    float pa[4] = {1.0f, 1.0f, 1.0f, 1.0f};
    float pb[4] = {1.0f, 1.0f, 1.0f, 1.0f};

    const ulonglong2* ha_base  = (const ulonglong2*)sh_ha  + eighth * 4;
    const ulonglong2* hcp_base = (const ulonglong2*)sh_hcp + eighth * 2;
    const bool do_p2 = (eighth == 0);    // warp-uniform

    #pragma unroll 1
    for (int c = 0; c < 25; c++) {       // chunk of 2 qubits: q0=2c, q1=2c+1
        uint64_t R0a[4], R1a[4], R0b[4], R1b[4];
        #pragma unroll
        for (int k = 0; k < 4; k++) {
            const float2* tp = (const float2*)(trow[k] + 6 * c);
            float2 v0 = tp[0], v1 = tp[1], v2 = tp[2];
            // q0: t=(v0.x, v0.y, v1.x); q1: t=(v1.y, v2.x, v2.y)
            float t2c0 = fmaxf(v1.x, 1e-12f);
            float t2c1 = fmaxf(v2.y, 1e-12f);
            float rc0, rc1;
            asm("rcp.approx.f32 %0, %1;" : "=f"(rc0) : "f"(t2c0));
            asm("rcp.approx.f32 %0, %1;" : "=f"(rc1) : "f"(t2c1));
            float r00 = v0.x * rc0, r10 = v0.y * rc0;
            float r01 = v1.y * rc1, r11 = v2.x * rc1;
            if (do_p2) {
                if (c <= 12) pa[k] *= t2c0; else pb[k] *= t2c0;
                if (c <= 11) pa[k] *= t2c1; else pb[k] *= t2c1;
            }
            asm("mov.b64 %0, {%1, %1};" : "=l"(R0a[k]) : "f"(r00));
            asm("mov.b64 %0, {%1, %1};" : "=l"(R1a[k]) : "f"(r10));
            asm("mov.b64 %0, {%1, %1};" : "=l"(R0b[k]) : "f"(r01));
            asm("mov.b64 %0, {%1, %1};" : "=l"(R1b[k]) : "f"(r11));
        }
        proc_q4(ha_base + (2*c)     * 32, hcp_base + (2*c)     * 16, R0a, R1a, acc);
        proc_q4(ha_base + (2*c + 1) * 32, hcp_base + (2*c + 1) * 16, R0b, R1b, acc);
    }

    // hr-weighted sums over this eighth's 8 heads, per word
    float part[4];
    const float* hre = sh_hr + eighth * 8;
    #pragma unroll
    for (int k = 0; k < 4; k++) {
        float p = 0.0f;
        #pragma unroll
        for (int j = 0; j < 4; j++) {
            float lo, hi;
            asm("mov.b64 {%0, %1}, %2;" : "=f"(lo), "=f"(hi) : "l"(acc[k][j]));
            p = fmaf(hre[2 * j], lo, p);
            p = fmaf(hre[2 * j + 1], hi, p);
        }
        part[k] = p;
    }

    if (eighth != 0) {
        #pragma unroll
        for (int k = 0; k < 4; k++)
            sh_part[(eighth - 1) * WORDS + w4[k]] = part[k];
    }
    __syncthreads();

    double v = 0.0;
    if (eighth == 0) {
        #pragma unroll
        for (int k = 0; k < 4; k++) {
            int n = base + w4[k];
            if (n < N) {
                float covf = part[k];
                #pragma unroll
                for (int e = 0; e < 7; e++) covf += sh_part[e * WORDS + w4[k]];
                double cov = (double)covf * (double)pa[k] * (double)pb[k];
                float c = coeff[n];
                v += (double)(c * c) / cov;
            }
        }
        #pragma unroll
        for (int off = 16; off; off >>= 1)
            v += __shfl_down_sync(0xFFFFFFFFu, v, off);
        if (lane == 0) sh_red[group] = v;
    }
    __syncthreads();
    if (tid == 0) {
        double s = sh_red[0] + sh_red[1];
        atomicAdd(&g_accum, s);
        __threadfence();
        unsigned int ticket = atomicAdd(&g_count, 1u);
        if (ticket == (unsigned int)(nblocks - 1)) {
            out[0] = (float)g_accum;
        }
    }
}

// ---------------------------------------------------------------------------
extern "C" void kernel_launch(void* const* d_in, const int* in_sizes, int n_in,
                              void* d_out, int out_size) {
    const float* pauli = (const float*)d_in[0];   // [N, 50, 3] f32
    const float* coeff = (const float*)d_in[1];   // [N] f32
    const float* heads = (const float*)d_in[2];   // [64, 50, 3] f32
    const float* hr    = (const float*)d_in[3];   // [64] f32
    const int N = in_sizes[1];

    const size_t smem = (size_t)SMEM_FLOATS * sizeof(float);   // 207680 B
    cudaFuncSetAttribute(main_kernel, cudaFuncAttributeMaxDynamicSharedMemorySize, (int)smem);

    prep_kernel<<<25, 128>>>(heads, hr);
    const int grid = (N + WORDS - 1) / WORDS;
    main_kernel<<<grid, THREADS, smem>>>(pauli, coeff, (float*)d_out, N, grid);
}

// round 12
// speedup vs baseline: 1.2144x; 1.2144x over previous
#include <cuda_runtime.h>
#include <cstdint>

// Problem constants (shapes fixed by the dataset)
#define SQ 50          // qubits
#define SP 3           // pauli basis
#define SS 64          // heads
#define WORDS 256      // words per block
#define THREADS 512    // 16 warps; warp quads split 64 heads, 2 words/thread
#define TROW 156       // padded row stride (28i mod 32: 8-lane LDS.128 phases disjoint)

// Packed heads: ha[q][j(32)][4] = {h0s0,h0s1,h1s0,h1s1}
//               hcp[q][jp(16)][4] = {h2(2jp)s0,h2(2jp)s1, h2(2jp+1)s0,h2(2jp+1)s1}
#define HA_TOTAL (SQ * 128)   // 6400
#define HCP_TOTAL (SQ * 64)   // 3200

// smem float offsets
#define OFF_HCP  HA_TOTAL               // 6400
#define OFF_HR   (OFF_HCP + HCP_TOTAL)  // 9600
#define OFF_PART (OFF_HR + SS)          // 9664 (3*256 = 768)
#define OFF_RED  (OFF_PART + 3*WORDS)   // 10432 (16 floats = 8 doubles)
#define OFF_T    (OFF_RED + 16)         // 10448 (41792 B, 16B aligned)
#define SMEM_FLOATS (OFF_T + WORDS * TROW)   // 50384 floats = 201536 B

__device__ double       g_accum;
__device__ unsigned int g_count;
__device__ float        g_ha[HA_TOTAL];
__device__ float        g_hcp[HCP_TOTAL];
__device__ float        g_hr[SS];

__device__ __forceinline__ float softplus20(float x) {
    float y = x * 20.0f;
    return fmaxf(y, 0.0f) + log1pf(expf(-fabsf(y)));
}

// ---------------------------------------------------------------------------
__global__ void prep_kernel(const float* __restrict__ heads_param,
                            const float* __restrict__ hr_param) {
    const int tid = threadIdx.x;

    if (blockIdx.x == 0 && tid == 0) { g_accum = 0.0; g_count = 0u; }

    __shared__ float s_hr[SS];
    if (tid < SS) s_hr[tid] = softplus20(hr_param[tid]);
    __syncthreads();
    if (blockIdx.x == 0 && tid < SS) {
        float s = 0.0f;
        #pragma unroll
        for (int i = 0; i < SS; i++) s += s_hr[i];
        s = fmaxf(s, 1e-12f);
        g_hr[tid] = (s_hr[tid] / s + 0.001f / (float)SS) / 1.001f;
    }

    const int stride = blockDim.x * gridDim.x;
    for (int i = blockIdx.x * blockDim.x + tid; i < SS * SQ; i += stride) {
        int s = i / SQ;
        int q = i - s * SQ;
        const float* hp = heads_param + (s * SQ + q) * SP;
        float h0 = softplus20(hp[0]);
        float h1 = softplus20(hp[1]);
        float h2 = softplus20(hp[2]);
        float inv = 1.0f / fmaxf(h0 + h1 + h2, 1e-12f);
        h0 *= inv; h1 *= inv; h2 *= inv;
        int j = s >> 1, o = s & 1;
        int jp = j >> 1, jo = j & 1;
        g_ha[q * 128 + j * 4 + 0 + o]       = h0;
        g_ha[q * 128 + j * 4 + 2 + o]       = h1;
        g_hcp[q * 64 + jp * 4 + jo * 2 + o] = h2;
    }
}

// ---------------------------------------------------------------------------
// Per-q step: 2 words x 8 head-pairs. dot = t2c*(h2 + h0*(t0/t2c) + h1*(t1/t2c))
// ---------------------------------------------------------------------------
__device__ __forceinline__ void proc_q2(
    bool do_p2, bool first_half,
    float t0a, float t1a, float t2a,     // word A
    float t0b, float t1b, float t2b,     // word B
    const ulonglong2* __restrict__ ha,   // this q, quarter offset: 8 entries
    const ulonglong2* __restrict__ hcp,  // this q, quarter offset: 4 entries
    uint64_t* __restrict__ accA, uint64_t* __restrict__ accB,
    float& pAa, float& pAb, float& pBa, float& pBb)
{
    float t2ca = fmaxf(t2a, 1e-12f);
    float t2cb = fmaxf(t2b, 1e-12f);
    float ra, rb;
    asm("rcp.approx.f32 %0, %1;" : "=f"(ra) : "f"(t2ca));
    asm("rcp.approx.f32 %0, %1;" : "=f"(rb) : "f"(t2cb));
    float r0a = t0a * ra, r1a = t1a * ra;
    float r0b = t0b * rb, r1b = t1b * rb;
    if (do_p2) {
        if (first_half) { pAa *= t2ca; pBa *= t2cb; }
        else            { pAb *= t2ca; pBb *= t2cb; }
    }

    uint64_t R0A, R1A, R0B, R1B;
    asm("mov.b64 %0, {%1, %1};" : "=l"(R0A) : "f"(r0a));
    asm("mov.b64 %0, {%1, %1};" : "=l"(R1A) : "f"(r1a));
    asm("mov.b64 %0, {%1, %1};" : "=l"(R0B) : "f"(r0b));
    asm("mov.b64 %0, {%1, %1};" : "=l"(R1B) : "f"(r1b));

    #pragma unroll
    for (int jp = 0; jp < 4; jp++) {
        ulonglong2 HcP = hcp[jp];          // {h2(2jp) pair, h2(2jp+1) pair}
        ulonglong2 Ha0 = ha[2 * jp];
        ulonglong2 Ha1 = ha[2 * jp + 1];
        uint64_t dA, dB;
        // j = 2jp
        asm("fma.rn.f32x2 %0, %1, %2, %3;" : "=l"(dA) : "l"(Ha0.x), "l"(R0A), "l"(HcP.x));
        asm("fma.rn.f32x2 %0, %1, %2, %3;" : "=l"(dB) : "l"(Ha0.x), "l"(R0B), "l"(HcP.x));
        asm("fma.rn.f32x2 %0, %1, %2, %3;" : "=l"(dA) : "l"(Ha0.y), "l"(R1A), "l"(dA));
        asm("fma.rn.f32x2 %0, %1, %2, %3;" : "=l"(dB) : "l"(Ha0.y), "l"(R1B), "l"(dB));
        asm("mul.rn.f32x2 %0, %1, %2;" : "=l"(accA[2*jp]) : "l"(accA[2*jp]), "l"(dA));
        asm("mul.rn.f32x2 %0, %1, %2;" : "=l"(accB[2*jp]) : "l"(accB[2*jp]), "l"(dB));
        // j = 2jp+1
        asm("fma.rn.f32x2 %0, %1, %2, %3;" : "=l"(dA) : "l"(Ha1.x), "l"(R0A), "l"(HcP.y));
        asm("fma.rn.f32x2 %0, %1, %2, %3;" : "=l"(dB) : "l"(Ha1.x), "l"(R0B), "l"(HcP.y));
        asm("fma.rn.f32x2 %0, %1, %2, %3;" : "=l"(dA) : "l"(Ha1.y), "l"(R1A), "l"(dA));
        asm("fma.rn.f32x2 %0, %1, %2, %3;" : "=l"(dB) : "l"(Ha1.y), "l"(R1B), "l"(dB));
        asm("mul.rn.f32x2 %0, %1, %2;" : "=l"(accA[2*jp+1]) : "l"(accA[2*jp+1]), "l"(dA));
        asm("mul.rn.f32x2 %0, %1, %2;" : "=l"(accB[2*jp+1]) : "l"(accB[2*jp+1]), "l"(dB));
    }
}

// ---------------------------------------------------------------------------
// Main: warp quad g=wid>>2 covers words [g*64, g*64+64); quarter = wid&3
// handles head pairs quarter*8..quarter*8+7. Thread words: lane, lane+32.
// ---------------------------------------------------------------------------
__global__ void __launch_bounds__(THREADS, 1)
main_kernel(const float* __restrict__ pauli,
            const float* __restrict__ coeff,
            float* __restrict__ out,
            int N, int nblocks) {
    extern __shared__ float smem[];
    float*  sh_ha   = smem;
    float*  sh_hcp  = smem + OFF_HCP;
    float*  sh_hr   = smem + OFF_HR;
    float*  sh_part = smem + OFF_PART;
    double* sh_red  = (double*)(smem + OFF_RED);
    float*  sh_t    = smem + OFF_T;

    const int tid  = threadIdx.x;
    const int wid  = tid >> 5;
    const int lane = tid & 31;

    // Stage heads tables
    {
        const float4* src = (const float4*)g_ha;
        float4*       dst = (float4*)sh_ha;
        #pragma unroll
        for (int i = tid; i < HA_TOTAL / 4; i += THREADS) dst[i] = src[i];
        const float4* src2 = (const float4*)g_hcp;
        float4*       dst2 = (float4*)sh_hcp;
        #pragma unroll
        for (int i = tid; i < HCP_TOTAL / 4; i += THREADS) dst2[i] = src2[i];
    }
    if (tid < SS) sh_hr[tid] = g_hr[tid];

    // Stage pauli tile: float2 coalesced reads, padded-row float2 scatter
    // (TROW even -> w*156 + 2k is always 8B-aligned; consecutive lanes hit
    //  consecutive bank pairs -> conflict-free STS.64)
    const int base  = blockIdx.x * WORDS;
    const int valid = min(WORDS, N - base);
    const float2* gsrc2 = (const float2*)(pauli + (size_t)base * (SQ * SP));
    for (int i = tid; i < valid * 75; i += THREADS) {
        int w = i / 75;
        int k = i - w * 75;
        *(float2*)(sh_t + w * TROW + 2 * k) = gsrc2[i];
    }
    __syncthreads();

    const int quarter = wid & 3;
    const int group   = wid >> 2;
    const int wA = group * 64 + lane;
    const int wB = wA + 32;
    const float* trowA = sh_t + wA * TROW;
    const float* trowB = sh_t + wB * TROW;
    const bool do_p2 = (quarter == 0);   // warp-uniform

    uint64_t accA[8], accB[8];
    #pragma unroll
    for (int j = 0; j < 8; j++) { accA[j] = 0x3F8000003F800000ull; accB[j] = accA[j]; }
    float pAa = 1.0f, pAb = 1.0f, pBa = 1.0f, pBb = 1.0f;

    const ulonglong2* ha_q  = (const ulonglong2*)sh_ha  + quarter * 8;   // + q*32
    const ulonglong2* hcp_q = (const ulonglong2*)sh_hcp + quarter * 4;   // + q*16

    const float4* tvA = (const float4*)trowA;
    const float4* tvB = (const float4*)trowB;
    #pragma unroll 4
    for (int c = 0; c < 12; c++) {
        float4 A0 = tvA[3*c+0], A1 = tvA[3*c+1], A2 = tvA[3*c+2];
        float4 B0 = tvB[3*c+0], B1 = tvB[3*c+1], B2 = tvB[3*c+2];
        const int q = 4 * c;
        proc_q2(do_p2, q + 0 < 25, A0.x, A0.y, A0.z, B0.x, B0.y, B0.z,
                ha_q + (q+0)*32, hcp_q + (q+0)*16, accA, accB, pAa, pAb, pBa, pBb);
        proc_q2(do_p2, q + 1 < 25, A0.w, A1.x, A1.y, B0.w, B1.x, B1.y,
                ha_q + (q+1)*32, hcp_q + (q+1)*16, accA, accB, pAa, pAb, pBa, pBb);
        proc_q2(do_p2, q + 2 < 25, A1.z, A1.w, A2.x, B1.z, B1.w, B2.x,
                ha_q + (q+2)*32, hcp_q + (q+2)*16, accA, accB, pAa, pAb, pBa, pBb);
        proc_q2(do_p2, q + 3 < 25, A2.y, A2.z, A2.w, B2.y, B2.z, B2.w,
                ha_q + (q+3)*32, hcp_q + (q+3)*16, accA, accB, pAa, pAb, pBa, pBb);
    }
    {   // q = 48, 49 (floats 144..149, 8B-aligned)
        const float2* a2 = (const float2*)(trowA + 144);
        const float2* b2 = (const float2*)(trowB + 144);
        float2 ua = a2[0], va = a2[1], wa2 = a2[2];
        float2 ub = b2[0], vb = b2[1], wb2 = b2[2];
        proc_q2(do_p2, false, ua.x, ua.y, va.x, ub.x, ub.y, vb.x,
                ha_q + 48*32, hcp_q + 48*16, accA, accB, pAa, pAb, pBa, pBb);
        proc_q2(do_p2, false, va.y, wa2.x, wa2.y, vb.y, wb2.x, wb2.y,
                ha_q + 49*32, hcp_q + 49*16, accA, accB, pAa, pAb, pBa, pBb);
    }

    // hr-weighted sums over this quarter's 16 heads
    float partA = 0.0f, partB = 0.0f;
    const float* hrq = sh_hr + quarter * 16;
    #pragma unroll
    for (int j = 0; j < 8; j++) {
        float lo, hi;
        asm("mov.b64 {%0, %1}, %2;" : "=f"(lo), "=f"(hi) : "l"(accA[j]));
        partA = fmaf(hrq[2 * j], lo, partA);
        partA = fmaf(hrq[2 * j + 1], hi, partA);
        asm("mov.b64 {%0, %1}, %2;" : "=f"(lo), "=f"(hi) : "l"(accB[j]));
        partB = fmaf(hrq[2 * j], lo, partB);
        partB = fmaf(hrq[2 * j + 1], hi, partB);
    }

    if (quarter != 0) {
        sh_part[(quarter - 1) * WORDS + wA] = partA;
        sh_part[(quarter - 1) * WORDS + wB] = partB;
    }
    __syncthreads();

    double v = 0.0;
    if (quarter == 0) {
        int nA = base + wA;
        if (nA < N) {
            float covf = partA + sh_part[wA] + sh_part[WORDS + wA] + sh_part[2 * WORDS + wA];
            double cov = (double)covf * (double)pAa * (double)pAb;
            float c = coeff[nA];
            v = (double)(c * c) / cov;
        }
        int nB = base + wB;
        if (nB < N) {
            float covf = partB + sh_part[wB] + sh_part[WORDS + wB] + sh_part[2 * WORDS + wB];
            double cov = (double)covf * (double)pBa * (double)pBb;
            float c = coeff[nB];
            v += (double)(c * c) / cov;
        }
        #pragma unroll
        for (int off = 16; off; off >>= 1)
            v += __shfl_down_sync(0xFFFFFFFFu, v, off);
        if (lane == 0) sh_red[group] = v;
    }
    __syncthreads();
    if (tid == 0) {
        double s = 0.0;
        #pragma unroll
        for (int w = 0; w < 4; w++) s += sh_red[w];
        atomicAdd(&g_accum, s);
        __threadfence();
        unsigned int ticket = atomicAdd(&g_count, 1u);
        if (ticket == (unsigned int)(nblocks - 1)) {
            out[0] = (float)g_accum;
        }
    }
}

// ---------------------------------------------------------------------------
extern "C" void kernel_launch(void* const* d_in, const int* in_sizes, int n_in,
                              void* d_out, int out_size) {
    const float* pauli = (const float*)d_in[0];   // [N, 50, 3] f32
    const float* coeff = (const float*)d_in[1];   // [N] f32
    const float* heads = (const float*)d_in[2];   // [64, 50, 3] f32
    const float* hr    = (const float*)d_in[3];   // [64] f32
    const int N = in_sizes[1];

    const size_t smem = (size_t)SMEM_FLOATS * sizeof(float);   // 201536 B
    cudaFuncSetAttribute(main_kernel, cudaFuncAttributeMaxDynamicSharedMemorySize, (int)smem);

    prep_kernel<<<50, 128>>>(heads, hr);
    const int grid = (N + WORDS - 1) / WORDS;
    main_kernel<<<grid, THREADS, smem>>>(pauli, coeff, (float*)d_out, N, grid);
}